// round 6
// baseline (speedup 1.0000x reference)
#include <cuda_runtime.h>
#include <math.h>

// ---------------------------------------------------------------------------
// Butterfly module, round 6.
//
// Butterfly kernel identical to round 5 (validated winner):
//   CTA = 16-row block x 512 cols, 256 threads, 16 x float2 per thread,
//   all 8 layers + activation thread-local, streaming cache hints.
//
// New: the scatter pass-through prepass (mark -> copy-uncovered) runs on a
// non-blocking side stream, concurrent with the butterfly (their write sets
// are disjoint: butterfly writes exactly the idx_out rows, copy writes only
// the complement; `data` is read-only). Event fork/join keeps this
// graph-capturable; stream/events are created on the first (uncaptured)
// correctness call only.
// ---------------------------------------------------------------------------

#define CURV2 0.01f   // CURVATURE^2 = 0.1^2

__device__ unsigned char g_covered[1 << 20];  // scatter coverage flags (init 0)

__device__ __forceinline__ float smooth_relu(float xa) {
    return 0.5f * (xa + sqrtf(fmaf(xa, xa, CURV2)));
}

__device__ __forceinline__ void rot2(float2& l, float2& h, float2 cs) {
    float2 nl, nh;
    nl.x = fmaf(cs.x, l.x, cs.y * h.x);  nh.x = fmaf(cs.x, h.x, -cs.y * l.x);
    nl.y = fmaf(cs.x, l.y, cs.y * h.y);  nh.y = fmaf(cs.x, h.y, -cs.y * l.y);
    l = nl; h = nh;
}

// One butterfly layer over the 16-row block, compile-time stride S.
// cs: 8 (cos,sin) pairs ordered by ascending low-row offset.
template <int S>
__device__ __forceinline__ void blayer16(float2 a[16], const float2* __restrict__ cs) {
    int p = 0;
#pragma unroll
    for (int o = 0; o < 16; ++o)
        if ((o & S) == 0) { rot2(a[o], a[o + S], cs[p++]); }
}

__global__ __launch_bounds__(256)
void butterfly_kernel(const float* __restrict__ data,
                      const float* __restrict__ angles,
                      const float* __restrict__ biases,
                      const int*   __restrict__ idx_in,
                      const int*   __restrict__ idx_out,
                      float*       __restrict__ out,
                      int N, int B)
{
    __shared__ float2 cs[64];    // [layer 0..7][pair 0..7] -> (cos, sin)
    __shared__ float  sb[8];
    __shared__ int    rin[16], rout[16];

    const int tid = threadIdx.x;
    const int blk = blockIdx.y;

    if (tid < 64) {
        int l = tid >> 3, p = tid & 7;
        float ang = angles[(size_t)l * (N >> 1) + blk * 8 + p];
        float s, c;
        sincosf(ang, &s, &c);
        cs[tid] = make_float2(c, s);
    }
    if (tid < 8)  sb[tid] = biases[blk * 8 + tid];
    if (tid < 16) {
        rin[tid]  = idx_in[blk * 16 + tid];
        rout[tid] = idx_out[blk * 16 + tid];
    }
    __syncthreads();

    const int col = blockIdx.x * 512 + tid * 2;

    // --- load 16 rows x float2 (coalesced: warp covers 256B per row) ---
    float2 a[16];
#pragma unroll
    for (int i = 0; i < 16; ++i)
        a[i] = __ldcs(reinterpret_cast<const float2*>(
                   data + (size_t)rin[i] * B + col));

    // --- input layers: strides 1,2,4,8 ---
    blayer16<1>(a, cs + 0);
    blayer16<2>(a, cs + 8);
    blayer16<4>(a, cs + 16);
    blayer16<8>(a, cs + 24);

    // --- fused bias + smooth relu on rows 0-7 of the block ---
#pragma unroll
    for (int i = 0; i < 8; ++i) {
        float b = sb[i];
        a[i].x = smooth_relu(a[i].x + b);
        a[i].y = smooth_relu(a[i].y + b);
    }

    // --- output layers: strides 1,2,4,8 ---
    blayer16<1>(a, cs + 32);
    blayer16<2>(a, cs + 40);
    blayer16<4>(a, cs + 48);
    blayer16<8>(a, cs + 56);

    // --- store (streaming) ---
#pragma unroll
    for (int i = 0; i < 16; ++i)
        __stcs(reinterpret_cast<float2*>(out + (size_t)rout[i] * B + col), a[i]);
}

// ---------------------------------------------------------------------------
// Pass-through prepass. mark sets flags; copy reads then CLEARS them (flag
// state returns to all-zero after every replay -> graph-deterministic).
// ---------------------------------------------------------------------------

__global__ void mark_flags_kernel(const int* __restrict__ idx_out, int N) {
    int i = blockIdx.x * blockDim.x + threadIdx.x;
    if (i < N) g_covered[idx_out[i]] = 1;
}

__global__ __launch_bounds__(256)
void copy_uncovered_kernel(const float* __restrict__ data,
                           float* __restrict__ out, int B, int R) {
    __shared__ unsigned char f[16];
    const int base = blockIdx.x * 16;
    if (threadIdx.x < 16) {
        int r = base + threadIdx.x;
        unsigned char c = (r < R) ? g_covered[r] : 1;
        f[threadIdx.x] = c;
        if (r < R) g_covered[r] = 0;      // self-reset for next replay
    }
    __syncthreads();
#pragma unroll 1
    for (int r = 0; r < 16; ++r) {
        if (f[r]) continue;
        int row = base + r;
        const float4* src = reinterpret_cast<const float4*>(data + (size_t)row * B);
        float4*       dst = reinterpret_cast<float4*>(out + (size_t)row * B);
        for (int i = threadIdx.x; i < (B >> 2); i += blockDim.x)
            dst[i] = src[i];
    }
}

extern "C" void kernel_launch(void* const* d_in, const int* in_sizes, int n_in,
                              void* d_out, int out_size)
{
    const float* data    = (const float*)d_in[0];
    const float* angles  = (const float*)d_in[1];
    const float* biases  = (const float*)d_in[2];
    const int*   idx_in  = (const int*)d_in[3];
    const int*   idx_out = (const int*)d_in[4];
    float*       out     = (float*)d_out;

    const int N = in_sizes[3];            // gathered rows (4096)
    const int B = in_sizes[0] / N;        // row width (8192)
    const int R = out_size / B;           // rows in out

    // Lazily created on the first call, which the harness performs BEFORE
    // graph capture, so no resource creation happens inside capture.
    static cudaStream_t side = nullptr;
    static cudaEvent_t  ev_fork = nullptr, ev_join = nullptr;
    if (side == nullptr) {
        cudaStreamCreateWithFlags(&side, cudaStreamNonBlocking);
        cudaEventCreateWithFlags(&ev_fork, cudaEventDisableTiming);
        cudaEventCreateWithFlags(&ev_join, cudaEventDisableTiming);
    }

    // Fork: prepass (mark -> copy) on side stream, butterfly on main stream.
    cudaEventRecord(ev_fork, 0);
    cudaStreamWaitEvent(side, ev_fork, 0);

    mark_flags_kernel<<<(N + 255) / 256, 256, 0, side>>>(idx_out, N);
    copy_uncovered_kernel<<<(R + 15) / 16, 256, 0, side>>>(data, out, B, R);
    cudaEventRecord(ev_join, side);

    // Main fused butterfly (concurrent with prepass; disjoint write sets).
    dim3 grid(B / 512, N / 16);
    butterfly_kernel<<<grid, 256>>>(data, angles, biases, idx_in, idx_out,
                                    out, N, B);

    // Join.
    cudaStreamWaitEvent(0, ev_join, 0);
}

// round 8
// speedup vs baseline: 1.2982x; 1.2982x over previous
#include <cuda_runtime.h>
#include <math.h>

// ---------------------------------------------------------------------------
// Butterfly module, round 7 (resubmit after infra failure).
//
// Data path identical to round 5 (validated, 55.7us): 16 rows x float2 per
// thread, all 8 layers + activation thread-local, streaming cache hints.
// Changes:
//   - cos/sin hoisted to a prep kernel (g_cs table): butterfly CTAs no longer
//     run 64 sincosf on their critical path before the first data load.
//   - each butterfly CTA processes TWO 512-col slices (amortizes prologue,
//     halves CTA count).
//   - prep kernel also marks scatter coverage (3 launches total, one stream).
// ---------------------------------------------------------------------------

#define CURV2 0.01f   // CURVATURE^2 = 0.1^2

__device__ float2        g_cs[1 << 15];       // [layer * N/2 + pair] -> (cos,sin)
__device__ unsigned char g_covered[1 << 20];  // scatter coverage flags (init 0)

__device__ __forceinline__ float smooth_relu(float xa) {
    return 0.5f * (xa + sqrtf(fmaf(xa, xa, CURV2)));
}

__device__ __forceinline__ void rot2(float2& l, float2& h, float2 cs) {
    float2 nl, nh;
    nl.x = fmaf(cs.x, l.x, cs.y * h.x);  nh.x = fmaf(cs.x, h.x, -cs.y * l.x);
    nl.y = fmaf(cs.x, l.y, cs.y * h.y);  nh.y = fmaf(cs.x, h.y, -cs.y * l.y);
    l = nl; h = nh;
}

// One butterfly layer over the 16-row block, compile-time stride S.
// cs: 8 (cos,sin) pairs ordered by ascending low-row offset.
template <int S>
__device__ __forceinline__ void blayer16(float2 a[16], const float2* __restrict__ cs) {
    int p = 0;
#pragma unroll
    for (int o = 0; o < 16; ++o)
        if ((o & S) == 0) { rot2(a[o], a[o + S], cs[p++]); }
}

__global__ __launch_bounds__(256)
void butterfly_kernel(const float* __restrict__ data,
                      const float* __restrict__ biases,
                      const int*   __restrict__ idx_in,
                      const int*   __restrict__ idx_out,
                      float*       __restrict__ out,
                      int N, int B)
{
    __shared__ float2 cs[64];    // [layer 0..7][pair 0..7] -> (cos, sin)
    __shared__ float  sb[8];
    __shared__ int    rin[16], rout[16];

    const int tid = threadIdx.x;
    const int blk = blockIdx.y;

    if (tid < 64) {
        int l = tid >> 3, p = tid & 7;
        cs[tid] = g_cs[l * (N >> 1) + blk * 8 + p];
    }
    if (tid < 8)  sb[tid] = biases[blk * 8 + tid];
    if (tid < 16) {
        rin[tid]  = idx_in[blk * 16 + tid];
        rout[tid] = idx_out[blk * 16 + tid];
    }
    __syncthreads();

    const int col0 = blockIdx.x * 1024 + tid * 2;

#pragma unroll 1
    for (int sub = 0; sub < 2; ++sub) {
        const int col = col0 + sub * 512;

        // --- load 16 rows x float2 (coalesced: warp covers 256B per row) ---
        float2 a[16];
#pragma unroll
        for (int i = 0; i < 16; ++i)
            a[i] = __ldcs(reinterpret_cast<const float2*>(
                       data + (size_t)rin[i] * B + col));

        // --- input layers: strides 1,2,4,8 ---
        blayer16<1>(a, cs + 0);
        blayer16<2>(a, cs + 8);
        blayer16<4>(a, cs + 16);
        blayer16<8>(a, cs + 24);

        // --- fused bias + smooth relu on rows 0-7 of the block ---
#pragma unroll
        for (int i = 0; i < 8; ++i) {
            float b = sb[i];
            a[i].x = smooth_relu(a[i].x + b);
            a[i].y = smooth_relu(a[i].y + b);
        }

        // --- output layers: strides 1,2,4,8 ---
        blayer16<1>(a, cs + 32);
        blayer16<2>(a, cs + 40);
        blayer16<4>(a, cs + 48);
        blayer16<8>(a, cs + 56);

        // --- store (streaming) ---
#pragma unroll
        for (int i = 0; i < 16; ++i)
            __stcs(reinterpret_cast<float2*>(out + (size_t)rout[i] * B + col),
                   a[i]);
    }
}

// ---------------------------------------------------------------------------
// Prep: cos/sin table + coverage marks in one kernel. copy-uncovered reads
// flags then CLEARS them (state returns to all-zero each replay; graph-safe).
// ---------------------------------------------------------------------------

__global__ void prep_kernel(const float* __restrict__ angles,
                            const int*   __restrict__ idx_out,
                            int nang, int N)
{
    int i = blockIdx.x * blockDim.x + threadIdx.x;
    if (i < nang) {
        float s, c;
        sincosf(angles[i], &s, &c);
        g_cs[i] = make_float2(c, s);
    }
    if (i < N) g_covered[idx_out[i]] = 1;
}

__global__ __launch_bounds__(256)
void copy_uncovered_kernel(const float* __restrict__ data,
                           float* __restrict__ out, int B, int R) {
    __shared__ unsigned char f[16];
    const int base = blockIdx.x * 16;
    if (threadIdx.x < 16) {
        int r = base + threadIdx.x;
        unsigned char c = (r < R) ? g_covered[r] : 1;
        f[threadIdx.x] = c;
        if (r < R) g_covered[r] = 0;      // self-reset for next replay
    }
    __syncthreads();
#pragma unroll 1
    for (int r = 0; r < 16; ++r) {
        if (f[r]) continue;
        int row = base + r;
        const float4* src = reinterpret_cast<const float4*>(data + (size_t)row * B);
        float4*       dst = reinterpret_cast<float4*>(out + (size_t)row * B);
        for (int i = threadIdx.x; i < (B >> 2); i += blockDim.x)
            dst[i] = src[i];
    }
}

extern "C" void kernel_launch(void* const* d_in, const int* in_sizes, int n_in,
                              void* d_out, int out_size)
{
    const float* data    = (const float*)d_in[0];
    const float* angles  = (const float*)d_in[1];
    const float* biases  = (const float*)d_in[2];
    const int*   idx_in  = (const int*)d_in[3];
    const int*   idx_out = (const int*)d_in[4];
    float*       out     = (float*)d_out;

    const int N    = in_sizes[3];          // gathered rows (4096)
    const int B    = in_sizes[0] / N;      // row width (8192)
    const int R    = out_size / B;         // rows in out
    const int nang = in_sizes[1];          // total angle count

    int prep_n = nang > N ? nang : N;
    prep_kernel<<<(prep_n + 255) / 256, 256>>>(angles, idx_out, nang, N);
    copy_uncovered_kernel<<<(R + 15) / 16, 256>>>(data, out, B, R);

    // main fused butterfly: CTA = 16 rows x 1024 cols (two 512-col slices)
    dim3 grid(B / 1024, N / 16);
    butterfly_kernel<<<grid, 256>>>(data, biases, idx_in, idx_out, out, N, B);
}

// round 9
// speedup vs baseline: 1.3696x; 1.0550x over previous
#include <cuda_runtime.h>
#include <math.h>

// ---------------------------------------------------------------------------
// Butterfly module, round 9.
//
// Butterfly data path identical to round 8 (best: 55.3us): 16 rows x float2
// per thread, all 8 layers + activation thread-local, streaming hints, two
// 512-col slices per CTA, cos/sin from precomputed g_cs table.
//
// Change: copy-uncovered pass fused into the butterfly kernel as tail
// blockIdx.y blocks (one per 16-row group, full width, x==0 only), removing
// one kernel launch (~4-5us launch floor each on this harness).
// Launches: prep (sincos table + coverage marks) -> fused butterfly+copy.
// ---------------------------------------------------------------------------

#define CURV2 0.01f   // CURVATURE^2 = 0.1^2

__device__ float2        g_cs[1 << 15];       // [layer * N/2 + pair] -> (cos,sin)
__device__ unsigned char g_covered[1 << 20];  // scatter coverage flags (init 0)

__device__ __forceinline__ float smooth_relu(float xa) {
    return 0.5f * (xa + sqrtf(fmaf(xa, xa, CURV2)));
}

__device__ __forceinline__ void rot2(float2& l, float2& h, float2 cs) {
    float2 nl, nh;
    nl.x = fmaf(cs.x, l.x, cs.y * h.x);  nh.x = fmaf(cs.x, h.x, -cs.y * l.x);
    nl.y = fmaf(cs.x, l.y, cs.y * h.y);  nh.y = fmaf(cs.x, h.y, -cs.y * l.y);
    l = nl; h = nh;
}

// One butterfly layer over the 16-row block, compile-time stride S.
// cs: 8 (cos,sin) pairs ordered by ascending low-row offset.
template <int S>
__device__ __forceinline__ void blayer16(float2 a[16], const float2* __restrict__ cs) {
    int p = 0;
#pragma unroll
    for (int o = 0; o < 16; ++o)
        if ((o & S) == 0) { rot2(a[o], a[o + S], cs[p++]); }
}

__global__ __launch_bounds__(256)
void butterfly_fused_kernel(const float* __restrict__ data,
                            const float* __restrict__ biases,
                            const int*   __restrict__ idx_in,
                            const int*   __restrict__ idx_out,
                            float*       __restrict__ out,
                            int N, int B, int NB, int R)
{
    const int tid = threadIdx.x;
    const int by  = blockIdx.y;

    // ---------------- tail blocks: pass-through copy of uncovered rows ------
    if (by >= NB) {
        if (blockIdx.x != 0) return;      // only one block per row-group
        __shared__ unsigned char f[16];
        const int base = (by - NB) * 16;
        if (tid < 16) {
            int r = base + tid;
            unsigned char c = (r < R) ? g_covered[r] : 1;
            f[tid] = c;
            if (r < R) g_covered[r] = 0;  // self-reset for next replay
        }
        __syncthreads();
#pragma unroll 1
        for (int r = 0; r < 16; ++r) {
            if (f[r]) continue;
            int row = base + r;
            const float4* src = reinterpret_cast<const float4*>(data + (size_t)row * B);
            float4*       dst = reinterpret_cast<float4*>(out + (size_t)row * B);
            for (int i = tid; i < (B >> 2); i += blockDim.x)
                dst[i] = src[i];
        }
        return;
    }

    // ---------------- butterfly blocks (identical to round 8) ---------------
    __shared__ float2 cs[64];    // [layer 0..7][pair 0..7] -> (cos, sin)
    __shared__ float  sb[8];
    __shared__ int    rin[16], rout[16];

    const int blk = by;

    if (tid < 64) {
        int l = tid >> 3, p = tid & 7;
        cs[tid] = g_cs[l * (N >> 1) + blk * 8 + p];
    }
    if (tid < 8)  sb[tid] = biases[blk * 8 + tid];
    if (tid < 16) {
        rin[tid]  = idx_in[blk * 16 + tid];
        rout[tid] = idx_out[blk * 16 + tid];
    }
    __syncthreads();

    const int col0 = blockIdx.x * 1024 + tid * 2;

#pragma unroll 1
    for (int sub = 0; sub < 2; ++sub) {
        const int col = col0 + sub * 512;

        // --- load 16 rows x float2 (coalesced: warp covers 256B per row) ---
        float2 a[16];
#pragma unroll
        for (int i = 0; i < 16; ++i)
            a[i] = __ldcs(reinterpret_cast<const float2*>(
                       data + (size_t)rin[i] * B + col));

        // --- input layers: strides 1,2,4,8 ---
        blayer16<1>(a, cs + 0);
        blayer16<2>(a, cs + 8);
        blayer16<4>(a, cs + 16);
        blayer16<8>(a, cs + 24);

        // --- fused bias + smooth relu on rows 0-7 of the block ---
#pragma unroll
        for (int i = 0; i < 8; ++i) {
            float b = sb[i];
            a[i].x = smooth_relu(a[i].x + b);
            a[i].y = smooth_relu(a[i].y + b);
        }

        // --- output layers: strides 1,2,4,8 ---
        blayer16<1>(a, cs + 32);
        blayer16<2>(a, cs + 40);
        blayer16<4>(a, cs + 48);
        blayer16<8>(a, cs + 56);

        // --- store (streaming) ---
#pragma unroll
        for (int i = 0; i < 16; ++i)
            __stcs(reinterpret_cast<float2*>(out + (size_t)rout[i] * B + col),
                   a[i]);
    }
}

// ---------------------------------------------------------------------------
// Prep: cos/sin table + coverage marks in one kernel.
// ---------------------------------------------------------------------------

__global__ void prep_kernel(const float* __restrict__ angles,
                            const int*   __restrict__ idx_out,
                            int nang, int N)
{
    int i = blockIdx.x * blockDim.x + threadIdx.x;
    if (i < nang) {
        float s, c;
        sincosf(angles[i], &s, &c);
        g_cs[i] = make_float2(c, s);
    }
    if (i < N) g_covered[idx_out[i]] = 1;
}

extern "C" void kernel_launch(void* const* d_in, const int* in_sizes, int n_in,
                              void* d_out, int out_size)
{
    const float* data    = (const float*)d_in[0];
    const float* angles  = (const float*)d_in[1];
    const float* biases  = (const float*)d_in[2];
    const int*   idx_in  = (const int*)d_in[3];
    const int*   idx_out = (const int*)d_in[4];
    float*       out     = (float*)d_out;

    const int N    = in_sizes[3];          // gathered rows (4096)
    const int B    = in_sizes[0] / N;      // row width (8192)
    const int R    = out_size / B;         // rows in out
    const int nang = in_sizes[1];          // total angle count
    const int NB   = N / 16;               // butterfly row-blocks
    const int CG   = (R + 15) / 16;        // copy row-groups

    int prep_n = nang > N ? nang : N;
    prep_kernel<<<(prep_n + 255) / 256, 256>>>(angles, idx_out, nang, N);

    // fused butterfly + pass-through copy:
    //   y in [0, NB)       : butterfly, CTA = 16 rows x 1024 cols
    //   y in [NB, NB+CG)   : copy-uncovered (x==0 only)
    dim3 grid(B / 1024, NB + CG);
    butterfly_fused_kernel<<<grid, 256>>>(data, biases, idx_in, idx_out, out,
                                          N, B, NB, R);
}

// round 10
// speedup vs baseline: 1.3882x; 1.0136x over previous
#include <cuda_runtime.h>
#include <math.h>

// ---------------------------------------------------------------------------
// Butterfly module, round 10. SINGLE kernel launch.
//
// - Packed f32x2 arithmetic (Blackwell FFMA2 via PTX fma.rn.f32x2): each
//   Givens rotation on a float2 column = 4 packed ops instead of 8 scalar.
// - __sincosf in the CTA prologue (fast intrinsic, tiny reg footprint) ->
//   no prep kernel, no device-global tables.
// - Scatter pass-through handled by tail blockIdx.y blocks that scan idx_out
//   directly (no coverage flag array, no extra launch).
// ---------------------------------------------------------------------------

typedef unsigned long long u64;

#define CURV2_PK  0x3C23D70A3C23D70AULL   // (0.01f, 0.01f)
#define HALF_PK   0x3F0000003F000000ULL   // (0.5f, 0.5f)

__device__ __forceinline__ u64 pack2(float x, float y) {
    u64 r; asm("mov.b64 %0, {%1, %2};" : "=l"(r) : "f"(x), "f"(y)); return r;
}
__device__ __forceinline__ float2 unpack2(u64 v) {
    float2 r; asm("mov.b64 {%0, %1}, %2;" : "=f"(r.x), "=f"(r.y) : "l"(v)); return r;
}
__device__ __forceinline__ u64 fma2(u64 a, u64 b, u64 c) {
    u64 d; asm("fma.rn.f32x2 %0, %1, %2, %3;" : "=l"(d) : "l"(a), "l"(b), "l"(c));
    return d;
}
__device__ __forceinline__ u64 mul2(u64 a, u64 b) {
    u64 d; asm("mul.rn.f32x2 %0, %1, %2;" : "=l"(d) : "l"(a), "l"(b)); return d;
}
__device__ __forceinline__ u64 add2(u64 a, u64 b) {
    u64 d; asm("add.rn.f32x2 %0, %1, %2;" : "=l"(d) : "l"(a), "l"(b)); return d;
}

struct Rot { u64 c2, s2, ns2; };

// One butterfly layer (stride S) on 16 packed-f32x2 rows.
// r: 8 rotation-constant triples ordered by ascending low-row offset.
template <int S>
__device__ __forceinline__ void blayer16(u64 a[16], const Rot* __restrict__ r) {
    int p = 0;
#pragma unroll
    for (int o = 0; o < 16; ++o) {
        if ((o & S) == 0) {
            u64 l = a[o], h = a[o + S];
            a[o]     = fma2(r[p].c2, l, mul2(r[p].s2, h));   //  c*l + s*h
            a[o + S] = fma2(r[p].c2, h, mul2(r[p].ns2, l));  //  c*h - s*l
            ++p;
        }
    }
}

__global__ __launch_bounds__(256)
void butterfly_fused_kernel(const float* __restrict__ data,
                            const float* __restrict__ angles,
                            const float* __restrict__ biases,
                            const int*   __restrict__ idx_in,
                            const int*   __restrict__ idx_out,
                            float*       __restrict__ out,
                            int N, int B, int NB, int R)
{
    const int tid = threadIdx.x;
    const int by  = blockIdx.y;

    // ---------------- tail blocks: pass-through copy of uncovered rows ------
    if (by >= NB) {
        if (blockIdx.x != 0) return;          // one block per 16-row group
        __shared__ unsigned int covmask;
        const int base = (by - NB) * 16;
        if (tid == 0) covmask = 0;
        __syncthreads();
        for (int i = tid; i < N; i += 256) {
            int r = idx_out[i] - base;
            if ((unsigned)r < 16u) atomicOr(&covmask, 1u << r);
        }
        __syncthreads();
        unsigned int cm = covmask;
#pragma unroll 1
        for (int r = 0; r < 16; ++r) {
            int row = base + r;
            if (row >= R || (cm >> r) & 1u) continue;
            const float4* src = reinterpret_cast<const float4*>(data + (size_t)row * B);
            float4*       dst = reinterpret_cast<float4*>(out + (size_t)row * B);
            for (int i = tid; i < (B >> 2); i += blockDim.x)
                dst[i] = src[i];
        }
        return;
    }

    // ---------------- butterfly blocks --------------------------------------
    __shared__ Rot srot[64];     // [layer 0..7][pair 0..7], pre-broadcast
    __shared__ u64 sb2[8];       // packed biases
    __shared__ int rin[16], rout[16];

    const int blk = by;

    if (tid < 64) {
        int l = tid >> 3, p = tid & 7;
        float ang = angles[(size_t)l * (N >> 1) + blk * 8 + p];
        float s, c;
        __sincosf(ang, &s, &c);
        srot[tid].c2  = pack2(c, c);
        srot[tid].s2  = pack2(s, s);
        srot[tid].ns2 = pack2(-s, -s);
    }
    if (tid < 8) {
        float b = biases[blk * 8 + tid];
        sb2[tid] = pack2(b, b);
    }
    if (tid < 16) {
        rin[tid]  = idx_in[blk * 16 + tid];
        rout[tid] = idx_out[blk * 16 + tid];
    }
    __syncthreads();

    const int col0 = blockIdx.x * 1024 + tid * 2;

#pragma unroll 1
    for (int sub = 0; sub < 2; ++sub) {
        const int col = col0 + sub * 512;

        // --- load 16 rows x f32x2 (coalesced, streaming) ---
        u64 a[16];
#pragma unroll
        for (int i = 0; i < 16; ++i)
            a[i] = __ldcs(reinterpret_cast<const u64*>(
                       data + (size_t)rin[i] * B + col));

        // --- input layers: strides 1,2,4,8 ---
        blayer16<1>(a, srot + 0);
        blayer16<2>(a, srot + 8);
        blayer16<4>(a, srot + 16);
        blayer16<8>(a, srot + 24);

        // --- fused bias + smooth relu on rows 0-7 ---
#pragma unroll
        for (int i = 0; i < 8; ++i) {
            u64 xa = add2(a[i], sb2[i]);
            u64 t  = fma2(xa, xa, CURV2_PK);     // xa^2 + curv^2
            float2 tf = unpack2(t);
            u64 sq = pack2(sqrtf(tf.x), sqrtf(tf.y));
            a[i] = mul2(HALF_PK, add2(xa, sq));  // 0.5*(xa + sqrt(...))
        }

        // --- output layers: strides 1,2,4,8 ---
        blayer16<1>(a, srot + 32);
        blayer16<2>(a, srot + 40);
        blayer16<4>(a, srot + 48);
        blayer16<8>(a, srot + 56);

        // --- store (streaming) ---
#pragma unroll
        for (int i = 0; i < 16; ++i)
            __stcs(reinterpret_cast<u64*>(out + (size_t)rout[i] * B + col), a[i]);
    }
}

extern "C" void kernel_launch(void* const* d_in, const int* in_sizes, int n_in,
                              void* d_out, int out_size)
{
    const float* data    = (const float*)d_in[0];
    const float* angles  = (const float*)d_in[1];
    const float* biases  = (const float*)d_in[2];
    const int*   idx_in  = (const int*)d_in[3];
    const int*   idx_out = (const int*)d_in[4];
    float*       out     = (float*)d_out;

    const int N  = in_sizes[3];            // gathered rows (4096)
    const int B  = in_sizes[0] / N;        // row width (8192)
    const int R  = out_size / B;           // rows in out
    const int NB = N / 16;                 // butterfly row-blocks
    const int CG = (R + 15) / 16;          // copy row-groups

    // single launch:
    //   y in [0, NB)     : butterfly, CTA = 16 rows x 1024 cols
    //   y in [NB, NB+CG) : pass-through copy (x==0 only; scans idx_out)
    dim3 grid(B / 1024, NB + CG);
    butterfly_fused_kernel<<<grid, 256>>>(data, angles, biases, idx_in,
                                          idx_out, out, N, B, NB, R);
}

// round 12
// speedup vs baseline: 1.3995x; 1.0081x over previous
#include <cuda_runtime.h>
#include <math.h>

// ---------------------------------------------------------------------------
// Butterfly module, round 12. SINGLE kernel launch.
// Same as round 11 but WITHOUT the forced __launch_bounds__(256,4) (prime
// suspect for the R11 hang/pathological-slowdown): natural allocation only.
//
// - Packed f32x2 math (Blackwell FFMA2): 4 packed ops + XOR per rotation.
// - Rotation constants as 16-byte {c2, s2} pairs -> one LDS.128 per rotation.
// - -s*l via 64-bit sign-flip XOR (ALU pipe idle).
// - Activation sqrt via __frsqrt_rn(t)*t (MUFU; rel err ~1e-6 << 1e-3).
// - Premultiplied row offsets in smem.
// - Scatter pass-through as tail blockIdx.y blocks scanning idx_out.
// ---------------------------------------------------------------------------

typedef unsigned long long u64;

#define CURV2_PK  0x3C23D70A3C23D70AULL   // (0.01f, 0.01f)
#define HALF_PK   0x3F0000003F000000ULL   // (0.5f, 0.5f)
#define SIGN2_PK  0x8000000080000000ULL   // packed sign bits

__device__ __forceinline__ u64 pack2(float x, float y) {
    u64 r; asm("mov.b64 %0, {%1, %2};" : "=l"(r) : "f"(x), "f"(y)); return r;
}
__device__ __forceinline__ float2 unpack2(u64 v) {
    float2 r; asm("mov.b64 {%0, %1}, %2;" : "=f"(r.x), "=f"(r.y) : "l"(v)); return r;
}
__device__ __forceinline__ u64 fma2(u64 a, u64 b, u64 c) {
    u64 d; asm("fma.rn.f32x2 %0, %1, %2, %3;" : "=l"(d) : "l"(a), "l"(b), "l"(c));
    return d;
}
__device__ __forceinline__ u64 mul2(u64 a, u64 b) {
    u64 d; asm("mul.rn.f32x2 %0, %1, %2;" : "=l"(d) : "l"(a), "l"(b)); return d;
}
__device__ __forceinline__ u64 add2(u64 a, u64 b) {
    u64 d; asm("add.rn.f32x2 %0, %1, %2;" : "=l"(d) : "l"(a), "l"(b)); return d;
}

// One butterfly layer (stride S) on 16 packed-f32x2 rows.
// srot: 8 {c2,s2} pairs (16B each) ordered by ascending low-row offset.
template <int S>
__device__ __forceinline__ void blayer16(u64 a[16],
                                         const ulonglong2* __restrict__ srot) {
    int p = 0;
#pragma unroll
    for (int o = 0; o < 16; ++o) {
        if ((o & S) == 0) {
            ulonglong2 r = srot[p++];          // LDS.128: {c2, s2}
            u64 l = a[o], h = a[o + S];
            a[o]     = fma2(r.x, l, mul2(r.y, h));               // c*l + s*h
            a[o + S] = fma2(r.x, h, mul2(r.y, l) ^ SIGN2_PK);    // c*h - s*l
        }
    }
}

__global__ __launch_bounds__(256)
void butterfly_fused_kernel(const float* __restrict__ data,
                            const float* __restrict__ angles,
                            const float* __restrict__ biases,
                            const int*   __restrict__ idx_in,
                            const int*   __restrict__ idx_out,
                            float*       __restrict__ out,
                            int N, int B, int NB, int R)
{
    const int tid = threadIdx.x;
    const int by  = blockIdx.y;

    // ---------------- tail blocks: pass-through copy of uncovered rows ------
    if (by >= NB) {
        if (blockIdx.x != 0) return;          // one block per 16-row group
        __shared__ unsigned int covmask;
        const int base = (by - NB) * 16;
        if (tid == 0) covmask = 0;
        __syncthreads();
        for (int i = tid; i < N; i += 256) {
            int r = idx_out[i] - base;
            if ((unsigned)r < 16u) atomicOr(&covmask, 1u << r);
        }
        __syncthreads();
        unsigned int cm = covmask;
#pragma unroll 1
        for (int r = 0; r < 16; ++r) {
            int row = base + r;
            if (row >= R || (cm >> r) & 1u) continue;
            const float4* src = reinterpret_cast<const float4*>(data + (size_t)row * B);
            float4*       dst = reinterpret_cast<float4*>(out + (size_t)row * B);
            for (int i = tid; i < (B >> 2); i += blockDim.x)
                dst[i] = src[i];
        }
        return;
    }

    // ---------------- butterfly blocks --------------------------------------
    __shared__ ulonglong2 srot[64];   // [layer 0..7][pair 0..7] = {c2, s2}
    __shared__ u64 sb2[8];            // packed biases
    __shared__ int oin[16], oout[16]; // premultiplied row offsets (elements)

    const int blk = by;

    if (tid < 64) {
        int l = tid >> 3, p = tid & 7;
        float ang = angles[(size_t)l * (N >> 1) + blk * 8 + p];
        float s, c;
        __sincosf(ang, &s, &c);
        srot[tid].x = pack2(c, c);
        srot[tid].y = pack2(s, s);
    }
    if (tid < 8) {
        float b = biases[blk * 8 + tid];
        sb2[tid] = pack2(b, b);
    }
    if (tid < 16) {
        oin[tid]  = idx_in [blk * 16 + tid] * B;
        oout[tid] = idx_out[blk * 16 + tid] * B;
    }
    __syncthreads();

    const int col0 = blockIdx.x * 1024 + tid * 2;

#pragma unroll 1
    for (int sub = 0; sub < 2; ++sub) {
        const int col = col0 + sub * 512;

        // --- load 16 rows x f32x2 (coalesced, streaming) ---
        u64 a[16];
#pragma unroll
        for (int i = 0; i < 16; ++i)
            a[i] = __ldcs(reinterpret_cast<const u64*>(data + (size_t)(oin[i] + col)));

        // --- input layers: strides 1,2,4,8 ---
        blayer16<1>(a, srot + 0);
        blayer16<2>(a, srot + 8);
        blayer16<4>(a, srot + 16);
        blayer16<8>(a, srot + 24);

        // --- fused bias + smooth relu on rows 0-7 ---
#pragma unroll
        for (int i = 0; i < 8; ++i) {
            u64 xa = add2(a[i], sb2[i]);
            u64 t  = fma2(xa, xa, CURV2_PK);          // xa^2 + curv^2  (>= 0.01)
            float2 tf = unpack2(t);
            float s0 = __frsqrt_rn(tf.x) * tf.x;      // sqrt(t) via MUFU
            float s1 = __frsqrt_rn(tf.y) * tf.y;
            a[i] = mul2(HALF_PK, add2(xa, pack2(s0, s1)));
        }

        // --- output layers: strides 1,2,4,8 ---
        blayer16<1>(a, srot + 32);
        blayer16<2>(a, srot + 40);
        blayer16<4>(a, srot + 48);
        blayer16<8>(a, srot + 56);

        // --- store (streaming) ---
#pragma unroll
        for (int i = 0; i < 16; ++i)
            __stcs(reinterpret_cast<u64*>(out + (size_t)(oout[i] + col)), a[i]);
    }
}

extern "C" void kernel_launch(void* const* d_in, const int* in_sizes, int n_in,
                              void* d_out, int out_size)
{
    const float* data    = (const float*)d_in[0];
    const float* angles  = (const float*)d_in[1];
    const float* biases  = (const float*)d_in[2];
    const int*   idx_in  = (const int*)d_in[3];
    const int*   idx_out = (const int*)d_in[4];
    float*       out     = (float*)d_out;

    const int N  = in_sizes[3];            // gathered rows (4096)
    const int B  = in_sizes[0] / N;        // row width (8192)
    const int R  = out_size / B;           // rows in out
    const int NB = N / 16;                 // butterfly row-blocks
    const int CG = (R + 15) / 16;          // copy row-groups

    // single launch:
    //   y in [0, NB)     : butterfly, CTA = 16 rows x 1024 cols
    //   y in [NB, NB+CG) : pass-through copy (x==0 only; scans idx_out)
    dim3 grid(B / 1024, NB + CG);
    butterfly_fused_kernel<<<grid, 256>>>(data, angles, biases, idx_in,
                                          idx_out, out, N, B, NB, R);
}

// round 13
// speedup vs baseline: 1.4381x; 1.0276x over previous
#include <cuda_runtime.h>
#include <math.h>

// ---------------------------------------------------------------------------
// Butterfly module, round 13. SINGLE kernel launch.
// R12 (51.3us) with ONE change: rotation hi-output computed via sub.rn.f32x2
// instead of fma2(mul2 ^ SIGN): 5 pure-FMA-pipe ops per rotation, zero ALU,
// no fma->alu->fma cross-pipe latency hops. (Kernel shown issue-bound:
// issue 62%, alu 34% from the 64-bit XORs.)
// ---------------------------------------------------------------------------

typedef unsigned long long u64;

#define CURV2_PK  0x3C23D70A3C23D70AULL   // (0.01f, 0.01f)
#define HALF_PK   0x3F0000003F000000ULL   // (0.5f, 0.5f)

__device__ __forceinline__ u64 pack2(float x, float y) {
    u64 r; asm("mov.b64 %0, {%1, %2};" : "=l"(r) : "f"(x), "f"(y)); return r;
}
__device__ __forceinline__ float2 unpack2(u64 v) {
    float2 r; asm("mov.b64 {%0, %1}, %2;" : "=f"(r.x), "=f"(r.y) : "l"(v)); return r;
}
__device__ __forceinline__ u64 fma2(u64 a, u64 b, u64 c) {
    u64 d; asm("fma.rn.f32x2 %0, %1, %2, %3;" : "=l"(d) : "l"(a), "l"(b), "l"(c));
    return d;
}
__device__ __forceinline__ u64 mul2(u64 a, u64 b) {
    u64 d; asm("mul.rn.f32x2 %0, %1, %2;" : "=l"(d) : "l"(a), "l"(b)); return d;
}
__device__ __forceinline__ u64 add2(u64 a, u64 b) {
    u64 d; asm("add.rn.f32x2 %0, %1, %2;" : "=l"(d) : "l"(a), "l"(b)); return d;
}
__device__ __forceinline__ u64 sub2(u64 a, u64 b) {
    u64 d; asm("sub.rn.f32x2 %0, %1, %2;" : "=l"(d) : "l"(a), "l"(b)); return d;
}

// One butterfly layer (stride S) on 16 packed-f32x2 rows.
// srot: 8 {c2,s2} pairs (16B each) ordered by ascending low-row offset.
//   lo = c*l + s*h    hi = c*h - s*l      (5 FMA-pipe ops, no ALU)
template <int S>
__device__ __forceinline__ void blayer16(u64 a[16],
                                         const ulonglong2* __restrict__ srot) {
    int p = 0;
#pragma unroll
    for (int o = 0; o < 16; ++o) {
        if ((o & S) == 0) {
            ulonglong2 r = srot[p++];          // LDS.128: {c2, s2}
            u64 l = a[o], h = a[o + S];
            a[o]     = fma2(r.x, l, mul2(r.y, h));
            a[o + S] = sub2(mul2(r.x, h), mul2(r.y, l));
        }
    }
}

__global__ __launch_bounds__(256)
void butterfly_fused_kernel(const float* __restrict__ data,
                            const float* __restrict__ angles,
                            const float* __restrict__ biases,
                            const int*   __restrict__ idx_in,
                            const int*   __restrict__ idx_out,
                            float*       __restrict__ out,
                            int N, int B, int NB, int R)
{
    const int tid = threadIdx.x;
    const int by  = blockIdx.y;

    // ---------------- tail blocks: pass-through copy of uncovered rows ------
    if (by >= NB) {
        if (blockIdx.x != 0) return;          // one block per 16-row group
        __shared__ unsigned int covmask;
        const int base = (by - NB) * 16;
        if (tid == 0) covmask = 0;
        __syncthreads();
        for (int i = tid; i < N; i += 256) {
            int r = idx_out[i] - base;
            if ((unsigned)r < 16u) atomicOr(&covmask, 1u << r);
        }
        __syncthreads();
        unsigned int cm = covmask;
#pragma unroll 1
        for (int r = 0; r < 16; ++r) {
            int row = base + r;
            if (row >= R || (cm >> r) & 1u) continue;
            const float4* src = reinterpret_cast<const float4*>(data + (size_t)row * B);
            float4*       dst = reinterpret_cast<float4*>(out + (size_t)row * B);
            for (int i = tid; i < (B >> 2); i += blockDim.x)
                dst[i] = src[i];
        }
        return;
    }

    // ---------------- butterfly blocks --------------------------------------
    __shared__ ulonglong2 srot[64];   // [layer 0..7][pair 0..7] = {c2, s2}
    __shared__ u64 sb2[8];            // packed biases
    __shared__ int oin[16], oout[16]; // premultiplied row offsets (elements)

    const int blk = by;

    if (tid < 64) {
        int l = tid >> 3, p = tid & 7;
        float ang = angles[(size_t)l * (N >> 1) + blk * 8 + p];
        float s, c;
        __sincosf(ang, &s, &c);
        srot[tid].x = pack2(c, c);
        srot[tid].y = pack2(s, s);
    }
    if (tid < 8) {
        float b = biases[blk * 8 + tid];
        sb2[tid] = pack2(b, b);
    }
    if (tid < 16) {
        oin[tid]  = idx_in [blk * 16 + tid] * B;
        oout[tid] = idx_out[blk * 16 + tid] * B;
    }
    __syncthreads();

    const int col0 = blockIdx.x * 1024 + tid * 2;

#pragma unroll 1
    for (int sub = 0; sub < 2; ++sub) {
        const int col = col0 + sub * 512;

        // --- load 16 rows x f32x2 (coalesced, streaming) ---
        u64 a[16];
#pragma unroll
        for (int i = 0; i < 16; ++i)
            a[i] = __ldcs(reinterpret_cast<const u64*>(data + (size_t)(oin[i] + col)));

        // --- input layers: strides 1,2,4,8 ---
        blayer16<1>(a, srot + 0);
        blayer16<2>(a, srot + 8);
        blayer16<4>(a, srot + 16);
        blayer16<8>(a, srot + 24);

        // --- fused bias + smooth relu on rows 0-7 ---
#pragma unroll
        for (int i = 0; i < 8; ++i) {
            u64 xa = add2(a[i], sb2[i]);
            u64 t  = fma2(xa, xa, CURV2_PK);          // xa^2 + curv^2  (>= 0.01)
            float2 tf = unpack2(t);
            float s0 = __frsqrt_rn(tf.x) * tf.x;      // sqrt(t) via MUFU
            float s1 = __frsqrt_rn(tf.y) * tf.y;
            a[i] = mul2(HALF_PK, add2(xa, pack2(s0, s1)));
        }

        // --- output layers: strides 1,2,4,8 ---
        blayer16<1>(a, srot + 32);
        blayer16<2>(a, srot + 40);
        blayer16<4>(a, srot + 48);
        blayer16<8>(a, srot + 56);

        // --- store (streaming) ---
#pragma unroll
        for (int i = 0; i < 16; ++i)
            __stcs(reinterpret_cast<u64*>(out + (size_t)(oout[i] + col)), a[i]);
    }
}

extern "C" void kernel_launch(void* const* d_in, const int* in_sizes, int n_in,
                              void* d_out, int out_size)
{
    const float* data    = (const float*)d_in[0];
    const float* angles  = (const float*)d_in[1];
    const float* biases  = (const float*)d_in[2];
    const int*   idx_in  = (const int*)d_in[3];
    const int*   idx_out = (const int*)d_in[4];
    float*       out     = (float*)d_out;

    const int N  = in_sizes[3];            // gathered rows (4096)
    const int B  = in_sizes[0] / N;        // row width (8192)
    const int R  = out_size / B;           // rows in out
    const int NB = N / 16;                 // butterfly row-blocks
    const int CG = (R + 15) / 16;          // copy row-groups

    // single launch:
    //   y in [0, NB)     : butterfly, CTA = 16 rows x 1024 cols
    //   y in [NB, NB+CG) : pass-through copy (x==0 only; scans idx_out)
    dim3 grid(B / 1024, NB + CG);
    butterfly_fused_kernel<<<grid, 256>>>(data, angles, biases, idx_in,
                                          idx_out, out, N, B, NB, R);
}